// round 7
// baseline (speedup 1.0000x reference)
#include <cuda_runtime.h>
#include <cstdint>

// ---------------- problem constants ----------------
constexpr int N_NODES  = 100000;
constexpr int N_EDGES  = 3200000;
constexpr int N_GRAPHS = 64;
constexpr int IN_CH  = 64;
constexpr int HID_CH = 128;
constexpr int LAT    = 32;
constexpr float EPS  = 1e-5f;
constexpr int SCAN_CHUNK = 1024;
constexpr int NBLK = (N_NODES + SCAN_CHUNK - 1) / SCAN_CHUNK;   // 98

// ---------------- scratch (device globals; referenced only from device code) --
__device__ __align__(16) int   g_count[N_NODES];
__device__ __align__(16) int   g_rowptr[N_NODES + 1];
__device__ __align__(16) int   g_cur[N_NODES];
__device__ __align__(16) int   g_src[N_EDGES];
__device__ __align__(16) int   g_bsum[NBLK];
__device__ __align__(16) int   g_boff[NBLK];
__device__ __align__(16) float g_dis[N_NODES];
__device__ __align__(16) float g_a  [(size_t)N_NODES * IN_CH];   // agg(x)   25.6MB
__device__ __align__(16) float g_big[(size_t)N_NODES * HID_CH];  // b1, then decoder hidden
__device__ __align__(16) float g_h2 [(size_t)N_NODES * LAT];     // b1@W2
__device__ __align__(16) float g_z  [(size_t)N_NODES * LAT];     // z_nodes
__device__ __align__(16) float g_s1[HID_CH];
__device__ __align__(16) float g_t1[HID_CH];
__device__ __align__(16) float g_s2[LAT];
__device__ __align__(16) float g_t2[LAT];
__device__ __align__(16) float g_sd[HID_CH];
__device__ __align__(16) float g_td[HID_CH];

// ---------------- zero the degree counters ----------------
__global__ void zero_kernel() {
    int i = blockIdx.x * blockDim.x + threadIdx.x;
    if (i < N_NODES) g_count[i] = 0;
}

// ---------------- BN scale/shift precompute (folds conv/fc bias in) ----------
// bn(a + cb) = a*s + ((cb - m)*s + b),  s = g*rsqrt(v+eps)
__global__ void prep_kernel(
    const float* __restrict__ conv1_b,
    const float* __restrict__ bn1_g, const float* __restrict__ bn1_b,
    const float* __restrict__ bn1_m, const float* __restrict__ bn1_v,
    const float* __restrict__ conv2_b,
    const float* __restrict__ bn2_g, const float* __restrict__ bn2_b,
    const float* __restrict__ bn2_m, const float* __restrict__ bn2_v,
    const float* __restrict__ fc1_b,
    const float* __restrict__ bnd_g, const float* __restrict__ bnd_b,
    const float* __restrict__ bnd_m, const float* __restrict__ bnd_v)
{
    int c = threadIdx.x;
    if (c < HID_CH) {
        float s = bn1_g[c] * rsqrtf(bn1_v[c] + EPS);
        g_s1[c] = s;
        g_t1[c] = (conv1_b[c] - bn1_m[c]) * s + bn1_b[c];
        float sd = bnd_g[c] * rsqrtf(bnd_v[c] + EPS);
        g_sd[c] = sd;
        g_td[c] = (fc1_b[c] - bnd_m[c]) * sd + bnd_b[c];
    }
    if (c < LAT) {
        float s = bn2_g[c] * rsqrtf(bn2_v[c] + EPS);
        g_s2[c] = s;
        g_t2[c] = (conv2_b[c] - bn2_m[c]) * s + bn2_b[c];
    }
}

// ---------------- CSR build (int atomics only; edge_index is INT32) ----------
__global__ void count_kernel(const int* __restrict__ ei) {
    int e = blockIdx.x * blockDim.x + threadIdx.x;
    if (e >= N_EDGES) return;
    atomicAdd(&g_count[ei[N_EDGES + e]], 1);
}

__global__ void dis_kernel() {
    int n = blockIdx.x * blockDim.x + threadIdx.x;
    if (n >= N_NODES) return;
    int d = g_count[n];
    g_dis[n] = d > 0 ? rsqrtf((float)d) : 0.0f;
}

__global__ void scanA_kernel() {
    __shared__ int sh[256];
    int t = threadIdx.x;
    int base = blockIdx.x * SCAN_CHUNK + t * 4;
    int s = 0;
    #pragma unroll
    for (int k = 0; k < 4; k++) {
        int i = base + k;
        if (i < N_NODES) s += g_count[i];
    }
    sh[t] = s; __syncthreads();
    for (int d = 128; d > 0; d >>= 1) {
        if (t < d) sh[t] += sh[t + d];
        __syncthreads();
    }
    if (t == 0) g_bsum[blockIdx.x] = sh[0];
}

__global__ void scanB_kernel() {
    if (threadIdx.x == 0) {
        int acc = 0;
        for (int b = 0; b < NBLK; b++) { g_boff[b] = acc; acc += g_bsum[b]; }
        g_rowptr[N_NODES] = acc;
    }
}

__global__ void scanC_kernel() {
    __shared__ int sh[256];
    int t = threadIdx.x;
    int base = blockIdx.x * SCAN_CHUNK + t * 4;
    int v[4]; int s = 0;
    #pragma unroll
    for (int k = 0; k < 4; k++) {
        int i = base + k;
        v[k] = (i < N_NODES) ? g_count[i] : 0;
        s += v[k];
    }
    sh[t] = s; __syncthreads();
    for (int d = 1; d < 256; d <<= 1) {
        int tmp = (t >= d) ? sh[t - d] : 0;
        __syncthreads();
        sh[t] += tmp;
        __syncthreads();
    }
    int off = g_boff[blockIdx.x] + sh[t] - s;   // exclusive
    #pragma unroll
    for (int k = 0; k < 4; k++) {
        int i = base + k;
        if (i < N_NODES) { g_rowptr[i] = off; g_cur[i] = off; off += v[k]; }
    }
}

__global__ void fill_kernel(const int* __restrict__ ei) {
    int e = blockIdx.x * blockDim.x + threadIdx.x;
    if (e >= N_EDGES) return;
    int r = ei[e];
    int c = ei[N_EDGES + e];
    int pos = atomicAdd(&g_cur[c], 1);
    g_src[pos] = r;
}

// ---------------- agg64: a[n] = dis[n] * sum_{e: col=n} x[row_e]*dis[row_e] ----
// warp per destination node, float2 per lane (64 channels)
__global__ void agg64_kernel(const float* __restrict__ x) {
    int w = (blockIdx.x * blockDim.x + threadIdx.x) >> 5;
    if (w >= N_NODES) return;
    int lane = threadIdx.x & 31;
    int beg = g_rowptr[w], end = g_rowptr[w + 1];
    float2 acc = make_float2(0.f, 0.f);
    for (int i = beg; i < end; i++) {
        int r = g_src[i];
        float nm = g_dis[r];
        float2 v = ((const float2*)(x + (size_t)r * IN_CH))[lane];
        acc.x = fmaf(v.x, nm, acc.x);
        acc.y = fmaf(v.y, nm, acc.y);
    }
    float dc = g_dis[w];
    acc.x *= dc; acc.y *= dc;
    ((float2*)(g_a + (size_t)w * IN_CH))[lane] = acc;
}

// ---------------- agg32: z[n] = relu(bn2( dis[n]*sum h2[row]*dis[row] )) ------
__global__ void agg32_kernel() {
    int w = (blockIdx.x * blockDim.x + threadIdx.x) >> 5;
    if (w >= N_NODES) return;
    int lane = threadIdx.x & 31;
    int beg = g_rowptr[w], end = g_rowptr[w + 1];
    float acc = 0.f;
    for (int i = beg; i < end; i++) {
        int r = g_src[i];
        acc = fmaf(g_h2[(size_t)r * LAT + lane], g_dis[r], acc);
    }
    acc *= g_dis[w];
    g_z[(size_t)w * LAT + lane] = fmaxf(fmaf(acc, g_s2[lane], g_t2[lane]), 0.f);
}

// ---------------- GEMM: out[N,COUT] = X[N,KIN] @ W[KIN,COUT] (+ epilogue) -----
// SRC: 1=g_a, 2=g_big, 3=g_z.  DST: 0=ext, 1=g_big, 2=g_h2.
// EPI: 0 none; 1 relu(acc*g_s1+g_t1); 2 relu(acc*g_sd+g_td); 3 acc+bias(ext)
template<int KIN, int COUT, int RPB, int EPI, int SRC, int DST>
__global__ void __launch_bounds__(256) gemm_kernel(const float* __restrict__ W,
                                                   const float* __restrict__ bias,
                                                   float* __restrict__ Oext)
{
    const float* X = (SRC == 1) ? (const float*)g_a
                   : (SRC == 2) ? (const float*)g_big : (const float*)g_z;
    float* O = (DST == 0) ? Oext : (DST == 1) ? (float*)g_big : (float*)g_h2;

    constexpr int CQ = COUT / 4;
    __shared__ alignas(16) float Wsh[KIN * COUT];
    __shared__ alignas(16) float Xsh[RPB * KIN];

    for (int i = threadIdx.x; i < KIN * COUT / 4; i += 256)
        ((float4*)Wsh)[i] = ((const float4*)W)[i];

    const size_t base = (size_t)blockIdx.x * RPB;   // N % RPB == 0
    const float4* Xg = (const float4*)(X + base * KIN);
    for (int i = threadIdx.x; i < RPB * KIN / 4; i += 256)
        ((float4*)Xsh)[i] = Xg[i];
    __syncthreads();

    constexpr int ITERS = (RPB * CQ + 255) / 256;
    #pragma unroll
    for (int it = 0; it < ITERS; it++) {
        int idx = it * 256 + threadIdx.x;
        int r  = idx / CQ;
        int cq = idx % CQ;
        const float* xr = Xsh + r * KIN;
        float4 acc = make_float4(0.f, 0.f, 0.f, 0.f);
        #pragma unroll
        for (int k = 0; k < KIN; k++) {
            float xv = xr[k];
            float4 w = ((const float4*)Wsh)[k * CQ + cq];
            acc.x = fmaf(xv, w.x, acc.x);
            acc.y = fmaf(xv, w.y, acc.y);
            acc.z = fmaf(xv, w.z, acc.z);
            acc.w = fmaf(xv, w.w, acc.w);
        }
        if (EPI == 1 || EPI == 2) {
            float4 sv = (EPI == 1) ? ((const float4*)g_s1)[cq] : ((const float4*)g_sd)[cq];
            float4 tv = (EPI == 1) ? ((const float4*)g_t1)[cq] : ((const float4*)g_td)[cq];
            acc.x = fmaxf(fmaf(acc.x, sv.x, tv.x), 0.f);
            acc.y = fmaxf(fmaf(acc.y, sv.y, tv.y), 0.f);
            acc.z = fmaxf(fmaf(acc.z, sv.z, tv.z), 0.f);
            acc.w = fmaxf(fmaf(acc.w, sv.w, tv.w), 0.f);
        } else if (EPI == 3) {
            float4 bv = *(const float4*)(bias + cq * 4);
            acc.x += bv.x; acc.y += bv.y; acc.z += bv.z; acc.w += bv.w;
        }
        ((float4*)O)[(base + r) * CQ + cq] = acc;
    }
}

// ---------------- graph mean pool: batch is SORTED int32 -> contiguous ranges -
// one block (256 thr) per graph; binary search boundaries; no atomics
__global__ void pool_kernel(const int* __restrict__ batch, float* __restrict__ out) {
    int g = blockIdx.x;
    __shared__ int s_lo, s_hi;
    if (threadIdx.x == 0) {
        int a = 0, b = N_NODES;
        while (a < b) { int m = (a + b) >> 1; if (batch[m] < g) a = m + 1; else b = m; }
        s_lo = a;
        b = N_NODES;
        while (a < b) { int m = (a + b) >> 1; if (batch[m] < g + 1) a = m + 1; else b = m; }
        s_hi = a;
    }
    __syncthreads();
    int lo = s_lo, hi = s_hi;
    int lane = threadIdx.x & 31, wid = threadIdx.x >> 5;   // 8 warps, lane = channel
    float acc = 0.f;
    for (int n = lo + wid; n < hi; n += 8)
        acc += g_z[(size_t)n * LAT + lane];
    __shared__ float sh[8][LAT];
    sh[wid][lane] = acc;
    __syncthreads();
    if (wid == 0) {
        float s = 0.f;
        #pragma unroll
        for (int k = 0; k < 8; k++) s += sh[k][lane];
        float cnt = (float)(hi - lo);
        out[g * LAT + lane] = s / fmaxf(cnt, 1.0f);
    }
}

// ---------------- launch: kernel launches ONLY ----------------
extern "C" void kernel_launch(void* const* d_in, const int* in_sizes, int n_in,
                              void* d_out, int out_size)
{
    const float* x     = (const float*)d_in[0];
    const int*   ei    = (const int*)d_in[1];      // int32! (jax x64 disabled)
    const int*   batch = (const int*)d_in[2];      // int32!
    const float* conv1_w = (const float*)d_in[3];
    const float* conv1_b = (const float*)d_in[4];
    const float* conv2_w = (const float*)d_in[5];
    const float* conv2_b = (const float*)d_in[6];
    const float* bn1_g = (const float*)d_in[7];
    const float* bn1_b = (const float*)d_in[8];
    const float* bn1_m = (const float*)d_in[9];
    const float* bn1_v = (const float*)d_in[10];
    const float* bn2_g = (const float*)d_in[11];
    const float* bn2_b = (const float*)d_in[12];
    const float* bn2_m = (const float*)d_in[13];
    const float* bn2_v = (const float*)d_in[14];
    const float* fc1_w = (const float*)d_in[15];
    const float* fc1_b = (const float*)d_in[16];
    const float* bnd_g = (const float*)d_in[17];
    const float* bnd_b = (const float*)d_in[18];
    const float* bnd_m = (const float*)d_in[19];
    const float* bnd_v = (const float*)d_in[20];
    const float* fc2_w = (const float*)d_in[21];
    const float* fc2_b = (const float*)d_in[22];
    float* out = (float*)d_out;

    zero_kernel<<<(N_NODES + 255) / 256, 256>>>();
    prep_kernel<<<1, 128>>>(conv1_b, bn1_g, bn1_b, bn1_m, bn1_v,
                            conv2_b, bn2_g, bn2_b, bn2_m, bn2_v,
                            fc1_b,   bnd_g, bnd_b, bnd_m, bnd_v);

    count_kernel<<<(N_EDGES + 255) / 256, 256>>>(ei);
    dis_kernel<<<(N_NODES + 255) / 256, 256>>>();
    scanA_kernel<<<NBLK, 256>>>();
    scanB_kernel<<<1, 32>>>();
    scanC_kernel<<<NBLK, 256>>>();
    fill_kernel<<<(N_EDGES + 255) / 256, 256>>>(ei);

    // a = A_norm @ x   (aggregate FIRST, 64 channels)
    agg64_kernel<<<(N_NODES * 32 + 255) / 256, 256>>>(x);
    // b1 = relu(bn1(a @ W1 + conv1_b))   -> g_big
    gemm_kernel<64, 128, 16, 1, 1, 1><<<N_NODES / 16, 256>>>(conv1_w, fc2_b, out);
    // h2 = b1 @ W2  (128 -> 32)
    gemm_kernel<128, 32, 32, 0, 2, 2><<<N_NODES / 32, 256>>>(conv2_w, fc2_b, out);
    // z = relu(bn2(A_norm @ h2 + conv2_b))
    agg32_kernel<<<(N_NODES * 32 + 255) / 256, 256>>>();
    // d = relu(bnd(z @ fc1_w + fc1_b))  -> g_big (reused)
    gemm_kernel<32, 128, 16, 2, 3, 1><<<N_NODES / 16, 256>>>(fc1_w, fc2_b, out);
    // x_hat = d @ fc2_w + fc2_b -> d_out[0 : 6.4M)
    gemm_kernel<128, 64, 16, 3, 2, 0><<<N_NODES / 16, 256>>>(fc2_w, fc2_b, out);
    // z_graph -> d_out[6.4M : 6.4M + 2048)
    pool_kernel<<<N_GRAPHS, 256>>>(batch, out + (size_t)N_NODES * IN_CH);
}

// round 8
// speedup vs baseline: 1.1859x; 1.1859x over previous
#include <cuda_runtime.h>
#include <cstdint>

// ---------------- problem constants ----------------
constexpr int N_NODES  = 100000;
constexpr int N_EDGES  = 3200000;
constexpr int N_GRAPHS = 64;
constexpr int IN_CH  = 64;
constexpr int HID_CH = 128;
constexpr int LAT    = 32;
constexpr float EPS  = 1e-5f;
constexpr int SCAN_CHUNK = 1024;
constexpr int NBLK = (N_NODES + SCAN_CHUNK - 1) / SCAN_CHUNK;   // 98

// ---------------- scratch (device globals) ----------------
__device__ __align__(16) int   g_count[N_NODES];
__device__ __align__(16) int   g_rowptr[N_NODES + 1];
__device__ __align__(16) int   g_cur[N_NODES];
__device__ __align__(16) int   g_src[N_EDGES];
__device__ __align__(16) int   g_bsum[NBLK];
__device__ __align__(16) int   g_boff[NBLK];
__device__ __align__(16) float g_dis[N_NODES];
__device__ __align__(16) float g_a  [(size_t)N_NODES * IN_CH];   // agg(x*dis)
__device__ __align__(16) float g_big[(size_t)N_NODES * HID_CH];  // xs -> b1 -> decoder hidden
__device__ __align__(16) float g_h2 [(size_t)N_NODES * LAT];     // (b1@W2)*dis[row]
__device__ __align__(16) float g_z  [(size_t)N_NODES * LAT];     // z_nodes
__device__ __align__(16) float g_s1[HID_CH];
__device__ __align__(16) float g_t1[HID_CH];
__device__ __align__(16) float g_s2[LAT];
__device__ __align__(16) float g_t2[LAT];
__device__ __align__(16) float g_sd[HID_CH];
__device__ __align__(16) float g_td[HID_CH];

// ---------------- zero the degree counters ----------------
__global__ void zero_kernel() {
    int i = blockIdx.x * blockDim.x + threadIdx.x;
    if (i < N_NODES) g_count[i] = 0;
}

// ---------------- BN scale/shift precompute (folds conv/fc bias in) ----------
__global__ void prep_kernel(
    const float* __restrict__ conv1_b,
    const float* __restrict__ bn1_g, const float* __restrict__ bn1_b,
    const float* __restrict__ bn1_m, const float* __restrict__ bn1_v,
    const float* __restrict__ conv2_b,
    const float* __restrict__ bn2_g, const float* __restrict__ bn2_b,
    const float* __restrict__ bn2_m, const float* __restrict__ bn2_v,
    const float* __restrict__ fc1_b,
    const float* __restrict__ bnd_g, const float* __restrict__ bnd_b,
    const float* __restrict__ bnd_m, const float* __restrict__ bnd_v)
{
    int c = threadIdx.x;
    if (c < HID_CH) {
        float s = bn1_g[c] * rsqrtf(bn1_v[c] + EPS);
        g_s1[c] = s;
        g_t1[c] = (conv1_b[c] - bn1_m[c]) * s + bn1_b[c];
        float sd = bnd_g[c] * rsqrtf(bnd_v[c] + EPS);
        g_sd[c] = sd;
        g_td[c] = (fc1_b[c] - bnd_m[c]) * sd + bnd_b[c];
    }
    if (c < LAT) {
        float s = bn2_g[c] * rsqrtf(bn2_v[c] + EPS);
        g_s2[c] = s;
        g_t2[c] = (conv2_b[c] - bn2_m[c]) * s + bn2_b[c];
    }
}

// ---------------- CSR build (edge_index is INT32) ----------------
__global__ void count_kernel(const int* __restrict__ ei) {
    int e = blockIdx.x * blockDim.x + threadIdx.x;
    if (e >= N_EDGES) return;
    atomicAdd(&g_count[ei[N_EDGES + e]], 1);
}

__global__ void dis_kernel() {
    int n = blockIdx.x * blockDim.x + threadIdx.x;
    if (n >= N_NODES) return;
    int d = g_count[n];
    g_dis[n] = d > 0 ? rsqrtf((float)d) : 0.0f;
}

__global__ void scanA_kernel() {
    __shared__ int sh[256];
    int t = threadIdx.x;
    int base = blockIdx.x * SCAN_CHUNK + t * 4;
    int s = 0;
    #pragma unroll
    for (int k = 0; k < 4; k++) {
        int i = base + k;
        if (i < N_NODES) s += g_count[i];
    }
    sh[t] = s; __syncthreads();
    for (int d = 128; d > 0; d >>= 1) {
        if (t < d) sh[t] += sh[t + d];
        __syncthreads();
    }
    if (t == 0) g_bsum[blockIdx.x] = sh[0];
}

__global__ void scanB_kernel() {
    if (threadIdx.x == 0) {
        int acc = 0;
        for (int b = 0; b < NBLK; b++) { g_boff[b] = acc; acc += g_bsum[b]; }
        g_rowptr[N_NODES] = acc;
    }
}

__global__ void scanC_kernel() {
    __shared__ int sh[256];
    int t = threadIdx.x;
    int base = blockIdx.x * SCAN_CHUNK + t * 4;
    int v[4]; int s = 0;
    #pragma unroll
    for (int k = 0; k < 4; k++) {
        int i = base + k;
        v[k] = (i < N_NODES) ? g_count[i] : 0;
        s += v[k];
    }
    sh[t] = s; __syncthreads();
    for (int d = 1; d < 256; d <<= 1) {
        int tmp = (t >= d) ? sh[t - d] : 0;
        __syncthreads();
        sh[t] += tmp;
        __syncthreads();
    }
    int off = g_boff[blockIdx.x] + sh[t] - s;   // exclusive
    #pragma unroll
    for (int k = 0; k < 4; k++) {
        int i = base + k;
        if (i < N_NODES) { g_rowptr[i] = off; g_cur[i] = off; off += v[k]; }
    }
}

__global__ void fill_kernel(const int* __restrict__ ei) {
    int e = blockIdx.x * blockDim.x + threadIdx.x;
    if (e >= N_EDGES) return;
    int r = ei[e];
    int c = ei[N_EDGES + e];
    int pos = atomicAdd(&g_cur[c], 1);
    g_src[pos] = r;
}

// ---------------- xs = x * dis[row]  -> g_big (free at this point) ------------
__global__ void scale_x_kernel(const float* __restrict__ x) {
    size_t i = (size_t)blockIdx.x * 256 + threadIdx.x;     // float4 index
    if (i >= (size_t)N_NODES * (IN_CH / 4)) return;
    int row = (int)(i >> 4);                                // 16 float4 per row
    float d = g_dis[row];
    float4 v = ((const float4*)x)[i];
    v.x *= d; v.y *= d; v.z *= d; v.w *= d;
    ((float4*)g_big)[i] = v;
}

// ---------------- agg64: a[n] = dis[n] * sum xs[src]  (warp/node, shfl idx) ---
__global__ void agg64_kernel() {
    int w = (blockIdx.x * blockDim.x + threadIdx.x) >> 5;
    if (w >= N_NODES) return;
    int lane = threadIdx.x & 31;
    int beg = g_rowptr[w], end = g_rowptr[w + 1];
    float2 acc = make_float2(0.f, 0.f);
    for (int base = beg; base < end; base += 32) {
        int cnt = min(32, end - base);
        int myr = (base + lane < end) ? g_src[base + lane] : 0;
        #pragma unroll 4
        for (int j = 0; j < cnt; j++) {
            int r = __shfl_sync(0xffffffffu, myr, j);
            float2 v = ((const float2*)(g_big + (size_t)r * IN_CH))[lane];
            acc.x += v.x;
            acc.y += v.y;
        }
    }
    float dc = g_dis[w];
    acc.x *= dc; acc.y *= dc;
    ((float2*)(g_a + (size_t)w * IN_CH))[lane] = acc;
}

// ---------------- agg32: z[n] = relu(bn2(dis[n] * sum h2[src])) ---------------
// h2 rows already pre-scaled by dis[row] in the gemm2 epilogue
__global__ void agg32_kernel() {
    int w = (blockIdx.x * blockDim.x + threadIdx.x) >> 5;
    if (w >= N_NODES) return;
    int lane = threadIdx.x & 31;
    int beg = g_rowptr[w], end = g_rowptr[w + 1];
    float acc = 0.f;
    for (int base = beg; base < end; base += 32) {
        int cnt = min(32, end - base);
        int myr = (base + lane < end) ? g_src[base + lane] : 0;
        #pragma unroll 4
        for (int j = 0; j < cnt; j++) {
            int r = __shfl_sync(0xffffffffu, myr, j);
            acc += g_h2[(size_t)r * LAT + lane];
        }
    }
    acc *= g_dis[w];
    g_z[(size_t)w * LAT + lane] = fmaxf(fmaf(acc, g_s2[lane], g_t2[lane]), 0.f);
}

// ---------------- register-blocked GEMM -------------------------------------
// out[N,COUT] = X[N,K] @ W[K,COUT], each thread computes TM rows x 4 cols.
// SRC: 1=g_a, 2=g_big, 3=g_z.  DST: 0=ext, 1=g_big, 2=g_h2.
// EPI: 0 none; 1 relu(*g_s1+g_t1); 2 relu(*g_sd+g_td); 3 +bias(ext); 4 *g_dis[row]
template<int K, int COUT, int TM, int EPI, int SRC, int DST>
__global__ void __launch_bounds__(256) gemm_kernel(const float* __restrict__ W,
                                                   const float* __restrict__ bias,
                                                   float* __restrict__ Oext)
{
    const float* X = (SRC == 1) ? (const float*)g_a
                   : (SRC == 2) ? (const float*)g_big : (const float*)g_z;
    float* O = (DST == 0) ? Oext : (DST == 1) ? (float*)g_big : (float*)g_h2;

    constexpr int CQ  = COUT / 4;      // col quads
    constexpr int RG  = 256 / CQ;      // row groups
    constexpr int RPB = RG * TM;       // rows per block

    __shared__ alignas(16) float Wsh[K * COUT];
    __shared__ alignas(16) float Xsh[RPB * K];

    const int tid = threadIdx.x;
    const size_t base = (size_t)blockIdx.x * RPB;

    for (int i = tid; i < K * COUT / 4; i += 256)
        ((float4*)Wsh)[i] = ((const float4*)W)[i];

    const float4* Xg = (const float4*)X;
    for (int i = tid; i < RPB * K / 4; i += 256) {
        int row = (i * 4) / K;
        float4 v = make_float4(0.f, 0.f, 0.f, 0.f);
        if (base + row < N_NODES) v = Xg[base * (K / 4) + i];
        ((float4*)Xsh)[i] = v;
    }
    __syncthreads();

    const int cx = tid % CQ;
    const int ry = tid / CQ;

    float4 acc[TM];
    #pragma unroll
    for (int m = 0; m < TM; m++) acc[m] = make_float4(0.f, 0.f, 0.f, 0.f);

    #pragma unroll 16
    for (int k = 0; k < K; k++) {
        float4 wv = ((const float4*)Wsh)[k * CQ + cx];
        #pragma unroll
        for (int m = 0; m < TM; m++) {
            float xv = Xsh[(ry * TM + m) * K + k];
            acc[m].x = fmaf(xv, wv.x, acc[m].x);
            acc[m].y = fmaf(xv, wv.y, acc[m].y);
            acc[m].z = fmaf(xv, wv.z, acc[m].z);
            acc[m].w = fmaf(xv, wv.w, acc[m].w);
        }
    }

    #pragma unroll
    for (int m = 0; m < TM; m++) {
        size_t row = base + ry * TM + m;
        if (row >= N_NODES) continue;
        float4 o = acc[m];
        if (EPI == 1 || EPI == 2) {
            float4 sv = (EPI == 1) ? ((const float4*)g_s1)[cx] : ((const float4*)g_sd)[cx];
            float4 tv = (EPI == 1) ? ((const float4*)g_t1)[cx] : ((const float4*)g_td)[cx];
            o.x = fmaxf(fmaf(o.x, sv.x, tv.x), 0.f);
            o.y = fmaxf(fmaf(o.y, sv.y, tv.y), 0.f);
            o.z = fmaxf(fmaf(o.z, sv.z, tv.z), 0.f);
            o.w = fmaxf(fmaf(o.w, sv.w, tv.w), 0.f);
        } else if (EPI == 3) {
            float4 bv = *(const float4*)(bias + cx * 4);
            o.x += bv.x; o.y += bv.y; o.z += bv.z; o.w += bv.w;
        } else if (EPI == 4) {
            float d = g_dis[row];
            o.x *= d; o.y *= d; o.z *= d; o.w *= d;
        }
        ((float4*)O)[row * CQ + cx] = o;
    }
}

// ---------------- graph mean pool: batch is SORTED int32 ----------------------
__global__ void pool_kernel(const int* __restrict__ batch, float* __restrict__ out) {
    int g = blockIdx.x;
    __shared__ int s_lo, s_hi;
    if (threadIdx.x == 0) {
        int a = 0, b = N_NODES;
        while (a < b) { int m = (a + b) >> 1; if (batch[m] < g) a = m + 1; else b = m; }
        s_lo = a;
        b = N_NODES;
        while (a < b) { int m = (a + b) >> 1; if (batch[m] < g + 1) a = m + 1; else b = m; }
        s_hi = a;
    }
    __syncthreads();
    int lo = s_lo, hi = s_hi;
    int lane = threadIdx.x & 31, wid = threadIdx.x >> 5;
    float acc = 0.f;
    for (int n = lo + wid; n < hi; n += 8)
        acc += g_z[(size_t)n * LAT + lane];
    __shared__ float sh[8][LAT];
    sh[wid][lane] = acc;
    __syncthreads();
    if (wid == 0) {
        float s = 0.f;
        #pragma unroll
        for (int k = 0; k < 8; k++) s += sh[k][lane];
        float cnt = (float)(hi - lo);
        out[g * LAT + lane] = s / fmaxf(cnt, 1.0f);
    }
}

// ---------------- launch: kernel launches ONLY ----------------
extern "C" void kernel_launch(void* const* d_in, const int* in_sizes, int n_in,
                              void* d_out, int out_size)
{
    const float* x     = (const float*)d_in[0];
    const int*   ei    = (const int*)d_in[1];      // int32
    const int*   batch = (const int*)d_in[2];      // int32
    const float* conv1_w = (const float*)d_in[3];
    const float* conv1_b = (const float*)d_in[4];
    const float* conv2_w = (const float*)d_in[5];
    const float* conv2_b = (const float*)d_in[6];
    const float* bn1_g = (const float*)d_in[7];
    const float* bn1_b = (const float*)d_in[8];
    const float* bn1_m = (const float*)d_in[9];
    const float* bn1_v = (const float*)d_in[10];
    const float* bn2_g = (const float*)d_in[11];
    const float* bn2_b = (const float*)d_in[12];
    const float* bn2_m = (const float*)d_in[13];
    const float* bn2_v = (const float*)d_in[14];
    const float* fc1_w = (const float*)d_in[15];
    const float* fc1_b = (const float*)d_in[16];
    const float* bnd_g = (const float*)d_in[17];
    const float* bnd_b = (const float*)d_in[18];
    const float* bnd_m = (const float*)d_in[19];
    const float* bnd_v = (const float*)d_in[20];
    const float* fc2_w = (const float*)d_in[21];
    const float* fc2_b = (const float*)d_in[22];
    float* out = (float*)d_out;

    zero_kernel<<<(N_NODES + 255) / 256, 256>>>();
    prep_kernel<<<1, 128>>>(conv1_b, bn1_g, bn1_b, bn1_m, bn1_v,
                            conv2_b, bn2_g, bn2_b, bn2_m, bn2_v,
                            fc1_b,   bnd_g, bnd_b, bnd_m, bnd_v);

    count_kernel<<<(N_EDGES + 255) / 256, 256>>>(ei);
    dis_kernel<<<(N_NODES + 255) / 256, 256>>>();
    scanA_kernel<<<NBLK, 256>>>();
    scanB_kernel<<<1, 32>>>();
    scanC_kernel<<<NBLK, 256>>>();
    fill_kernel<<<(N_EDGES + 255) / 256, 256>>>(ei);

    // xs = x * dis[row]  -> g_big
    scale_x_kernel<<<(N_NODES * (IN_CH / 4) + 255) / 256, 256>>>(x);
    // a = dis[n] * sum xs[src]
    agg64_kernel<<<(N_NODES * 32 + 255) / 256, 256>>>();
    // b1 = relu(bn1(a @ W1 + conv1_b))  -> g_big   [TM=4, RPB=32]
    gemm_kernel<64, 128, 4, 1, 1, 1><<<(N_NODES + 31) / 32, 256>>>(conv1_w, fc2_b, out);
    // h2 = (b1 @ W2) * dis[row]  -> g_h2           [TM=2, RPB=64]
    gemm_kernel<128, 32, 2, 4, 2, 2><<<(N_NODES + 63) / 64, 256>>>(conv2_w, fc2_b, out);
    // z = relu(bn2(dis[n] * sum h2[src] + conv2_b))
    agg32_kernel<<<(N_NODES * 32 + 255) / 256, 256>>>();
    // d = relu(bnd(z @ fc1_w + fc1_b))  -> g_big   [TM=4, RPB=32]
    gemm_kernel<32, 128, 4, 2, 3, 1><<<(N_NODES + 31) / 32, 256>>>(fc1_w, fc2_b, out);
    // x_hat = d @ fc2_w + fc2_b -> d_out           [TM=2, RPB=32]
    gemm_kernel<128, 64, 2, 3, 2, 0><<<(N_NODES + 31) / 32, 256>>>(fc2_w, fc2_b, out);
    // z_graph -> d_out[6.4M:]
    pool_kernel<<<N_GRAPHS, 256>>>(batch, out + (size_t)N_NODES * IN_CH);
}

// round 10
// speedup vs baseline: 1.2611x; 1.0634x over previous
#include <cuda_runtime.h>
#include <cstdint>

// ---------------- problem constants ----------------
constexpr int N_NODES  = 100000;
constexpr int N_EDGES  = 3200000;
constexpr int N_GRAPHS = 64;
constexpr int IN_CH  = 64;
constexpr int HID_CH = 128;
constexpr int LAT    = 32;
constexpr float EPS  = 1e-5f;
constexpr int SCAN_CHUNK = 1024;
constexpr int NBLK = (N_NODES + SCAN_CHUNK - 1) / SCAN_CHUNK;   // 98

// ---------------- scratch (device globals) ----------------
__device__ __align__(16) int   g_count[N_NODES];
__device__ __align__(16) int   g_rowptr[N_NODES + 1];
__device__ __align__(16) int   g_cur[N_NODES];
__device__ __align__(16) int   g_src[N_EDGES];
__device__ __align__(16) int   g_bsum[NBLK];
__device__ __align__(16) int   g_boff[NBLK];
__device__ __align__(16) float g_dis[N_NODES];
__device__ __align__(16) float g_a  [(size_t)N_NODES * IN_CH];   // agg(x*dis)
__device__ __align__(16) float g_big[(size_t)N_NODES * HID_CH];  // xs -> b1 -> decoder hidden
__device__ __align__(16) float g_h2 [(size_t)N_NODES * LAT];     // (b1@W2)*dis[row]
__device__ __align__(16) float g_z  [(size_t)N_NODES * LAT];     // z_nodes
__device__ __align__(16) float g_s1[HID_CH];
__device__ __align__(16) float g_t1[HID_CH];
__device__ __align__(16) float g_s2[LAT];
__device__ __align__(16) float g_t2[LAT];
__device__ __align__(16) float g_sd[HID_CH];
__device__ __align__(16) float g_td[HID_CH];

// ---------------- zero counters + BN prep (fused) ----------------
__global__ void zero_prep_kernel(
    const float* __restrict__ conv1_b,
    const float* __restrict__ bn1_g, const float* __restrict__ bn1_b,
    const float* __restrict__ bn1_m, const float* __restrict__ bn1_v,
    const float* __restrict__ conv2_b,
    const float* __restrict__ bn2_g, const float* __restrict__ bn2_b,
    const float* __restrict__ bn2_m, const float* __restrict__ bn2_v,
    const float* __restrict__ fc1_b,
    const float* __restrict__ bnd_g, const float* __restrict__ bnd_b,
    const float* __restrict__ bnd_m, const float* __restrict__ bnd_v)
{
    int i = blockIdx.x * blockDim.x + threadIdx.x;
    if (i < N_NODES) g_count[i] = 0;
    if (blockIdx.x == 0) {
        int c = threadIdx.x;
        if (c < HID_CH) {
            float s = bn1_g[c] * rsqrtf(bn1_v[c] + EPS);
            g_s1[c] = s;
            g_t1[c] = (conv1_b[c] - bn1_m[c]) * s + bn1_b[c];
            float sd = bnd_g[c] * rsqrtf(bnd_v[c] + EPS);
            g_sd[c] = sd;
            g_td[c] = (fc1_b[c] - bnd_m[c]) * sd + bnd_b[c];
        }
        if (c < LAT) {
            float s = bn2_g[c] * rsqrtf(bn2_v[c] + EPS);
            g_s2[c] = s;
            g_t2[c] = (conv2_b[c] - bn2_m[c]) * s + bn2_b[c];
        }
    }
}

// ---------------- CSR build (edge_index is INT32) ----------------
__global__ void count_kernel(const int* __restrict__ ei) {
    int e = blockIdx.x * blockDim.x + threadIdx.x;
    if (e >= N_EDGES) return;
    atomicAdd(&g_count[ei[N_EDGES + e]], 1);
}

// per-chunk sums + dis (fused)
__global__ void scanA_kernel() {
    __shared__ int sh[256];
    int t = threadIdx.x;
    int base = blockIdx.x * SCAN_CHUNK + t * 4;
    int s = 0;
    #pragma unroll
    for (int k = 0; k < 4; k++) {
        int i = base + k;
        if (i < N_NODES) {
            int d = g_count[i];
            s += d;
            g_dis[i] = d > 0 ? rsqrtf((float)d) : 0.0f;
        }
    }
    sh[t] = s; __syncthreads();
    for (int d = 128; d > 0; d >>= 1) {
        if (t < d) sh[t] += sh[t + d];
        __syncthreads();
    }
    if (t == 0) g_bsum[blockIdx.x] = sh[0];
}

__global__ void scanB_kernel() {
    if (threadIdx.x == 0) {
        int acc = 0;
        for (int b = 0; b < NBLK; b++) { g_boff[b] = acc; acc += g_bsum[b]; }
        g_rowptr[N_NODES] = acc;
    }
}

__global__ void scanC_kernel() {
    __shared__ int sh[256];
    int t = threadIdx.x;
    int base = blockIdx.x * SCAN_CHUNK + t * 4;
    int v[4]; int s = 0;
    #pragma unroll
    for (int k = 0; k < 4; k++) {
        int i = base + k;
        v[k] = (i < N_NODES) ? g_count[i] : 0;
        s += v[k];
    }
    sh[t] = s; __syncthreads();
    for (int d = 1; d < 256; d <<= 1) {
        int tmp = (t >= d) ? sh[t - d] : 0;
        __syncthreads();
        sh[t] += tmp;
        __syncthreads();
    }
    int off = g_boff[blockIdx.x] + sh[t] - s;   // exclusive
    #pragma unroll
    for (int k = 0; k < 4; k++) {
        int i = base + k;
        if (i < N_NODES) { g_rowptr[i] = off; g_cur[i] = off; off += v[k]; }
    }
}

__global__ void fill_kernel(const int* __restrict__ ei) {
    int e = blockIdx.x * blockDim.x + threadIdx.x;
    if (e >= N_EDGES) return;
    int r = ei[e];
    int c = ei[N_EDGES + e];
    int pos = atomicAdd(&g_cur[c], 1);
    g_src[pos] = r;
}

// ---------------- xs = x * dis[row]  -> g_big ------------
__global__ void scale_x_kernel(const float* __restrict__ x) {
    int i = blockIdx.x * 256 + threadIdx.x;                // float4 index (< 1.6M)
    if (i >= N_NODES * (IN_CH / 4)) return;
    int row = i >> 4;                                      // 16 float4 per row
    float d = g_dis[row];
    float4 v = ((const float4*)x)[i];
    v.x *= d; v.y *= d; v.z *= d; v.w *= d;
    ((float4*)g_big)[i] = v;
}

// ---------------- agg64: a[n] = dis[n] * sum xs[src]  (warp/node) -------------
// full 32-edge batches fully unrolled for high MLP; short tail after
__global__ void agg64_kernel() {
    int w = (blockIdx.x * blockDim.x + threadIdx.x) >> 5;
    if (w >= N_NODES) return;
    int lane = threadIdx.x & 31;
    int beg = g_rowptr[w], end = g_rowptr[w + 1];
    float2 acc = make_float2(0.f, 0.f);
    int i = beg;
    for (; i + 32 <= end; i += 32) {
        int myr = g_src[i + lane];
        #pragma unroll
        for (int j = 0; j < 32; j++) {
            int r = __shfl_sync(0xffffffffu, myr, j);
            float2 v = ((const float2*)g_big)[r * (IN_CH / 2) + lane];
            acc.x += v.x;
            acc.y += v.y;
        }
    }
    if (i < end) {
        int cnt = end - i;
        int myr = (i + lane < end) ? g_src[i + lane] : 0;
        #pragma unroll 4
        for (int j = 0; j < cnt; j++) {
            int r = __shfl_sync(0xffffffffu, myr, j);
            float2 v = ((const float2*)g_big)[r * (IN_CH / 2) + lane];
            acc.x += v.x;
            acc.y += v.y;
        }
    }
    float dc = g_dis[w];
    acc.x *= dc; acc.y *= dc;
    ((float2*)g_a)[w * (IN_CH / 2) + lane] = acc;
}

// ---------------- agg32: z[n] = relu(bn2(dis[n] * sum h2[src])) ---------------
__global__ void agg32_kernel() {
    int w = (blockIdx.x * blockDim.x + threadIdx.x) >> 5;
    if (w >= N_NODES) return;
    int lane = threadIdx.x & 31;
    int beg = g_rowptr[w], end = g_rowptr[w + 1];
    float acc = 0.f;
    int i = beg;
    for (; i + 32 <= end; i += 32) {
        int myr = g_src[i + lane];
        #pragma unroll
        for (int j = 0; j < 32; j++) {
            int r = __shfl_sync(0xffffffffu, myr, j);
            acc += g_h2[r * LAT + lane];
        }
    }
    if (i < end) {
        int cnt = end - i;
        int myr = (i + lane < end) ? g_src[i + lane] : 0;
        #pragma unroll 4
        for (int j = 0; j < cnt; j++) {
            int r = __shfl_sync(0xffffffffu, myr, j);
            acc += g_h2[r * LAT + lane];
        }
    }
    acc *= g_dis[w];
    g_z[w * LAT + lane] = fmaxf(fmaf(acc, g_s2[lane], g_t2[lane]), 0.f);
}

// ---------------- register-blocked GEMM -------------------------------------
// out[N,COUT] = X[N,K] @ W[K,COUT], each thread computes TM rows x 4 cols.
// SRC: 1=g_a, 2=g_big, 3=g_z.  DST: 0=ext, 1=g_big, 2=g_h2.
// EPI: 0 none; 1 relu(*g_s1+g_t1); 2 relu(*g_sd+g_td); 3 +bias(ext); 4 *g_dis[row]
template<int K, int COUT, int TM, int EPI, int SRC, int DST>
__global__ void __launch_bounds__(256) gemm_kernel(const float* __restrict__ W,
                                                   const float* __restrict__ bias,
                                                   float* __restrict__ Oext)
{
    const float* X = (SRC == 1) ? (const float*)g_a
                   : (SRC == 2) ? (const float*)g_big : (const float*)g_z;
    float* O = (DST == 0) ? Oext : (DST == 1) ? (float*)g_big : (float*)g_h2;

    constexpr int CQ  = COUT / 4;      // col quads
    constexpr int RG  = 256 / CQ;      // row groups
    constexpr int RPB = RG * TM;       // rows per block

    __shared__ alignas(16) float Wsh[K * COUT];
    __shared__ alignas(16) float Xsh[RPB * K];

    const int tid = threadIdx.x;
    const int base = blockIdx.x * RPB;

    for (int i = tid; i < K * COUT / 4; i += 256)
        ((float4*)Wsh)[i] = ((const float4*)W)[i];

    const float4* Xg = (const float4*)X;
    for (int i = tid; i < RPB * K / 4; i += 256) {
        int row = (i * 4) / K;
        float4 v = make_float4(0.f, 0.f, 0.f, 0.f);
        if (base + row < N_NODES) v = Xg[base * (K / 4) + i];
        ((float4*)Xsh)[i] = v;
    }
    __syncthreads();

    const int cx = tid % CQ;
    const int ry = tid / CQ;

    float4 acc[TM];
    #pragma unroll
    for (int m = 0; m < TM; m++) acc[m] = make_float4(0.f, 0.f, 0.f, 0.f);

    #pragma unroll 8
    for (int k = 0; k < K; k++) {
        float4 wv = ((const float4*)Wsh)[k * CQ + cx];
        #pragma unroll
        for (int m = 0; m < TM; m++) {
            float xv = Xsh[(ry * TM + m) * K + k];
            acc[m].x = fmaf(xv, wv.x, acc[m].x);
            acc[m].y = fmaf(xv, wv.y, acc[m].y);
            acc[m].z = fmaf(xv, wv.z, acc[m].z);
            acc[m].w = fmaf(xv, wv.w, acc[m].w);
        }
    }

    #pragma unroll
    for (int m = 0; m < TM; m++) {
        int row = base + ry * TM + m;
        if (row >= N_NODES) continue;
        float4 o = acc[m];
        if (EPI == 1 || EPI == 2) {
            float4 sv = (EPI == 1) ? ((const float4*)g_s1)[cx] : ((const float4*)g_sd)[cx];
            float4 tv = (EPI == 1) ? ((const float4*)g_t1)[cx] : ((const float4*)g_td)[cx];
            o.x = fmaxf(fmaf(o.x, sv.x, tv.x), 0.f);
            o.y = fmaxf(fmaf(o.y, sv.y, tv.y), 0.f);
            o.z = fmaxf(fmaf(o.z, sv.z, tv.z), 0.f);
            o.w = fmaxf(fmaf(o.w, sv.w, tv.w), 0.f);
        } else if (EPI == 3) {
            float4 bv = *(const float4*)(bias + cx * 4);
            o.x += bv.x; o.y += bv.y; o.z += bv.z; o.w += bv.w;
        } else if (EPI == 4) {
            float d = g_dis[row];
            o.x *= d; o.y *= d; o.z *= d; o.w *= d;
        }
        ((float4*)O)[(size_t)row * CQ + cx] = o;
    }
}

// ---------------- graph mean pool: batch is SORTED int32 ----------------------
__global__ void pool_kernel(const int* __restrict__ batch, float* __restrict__ out) {
    int g = blockIdx.x;
    __shared__ int s_lo, s_hi;
    if (threadIdx.x == 0) {
        int a = 0, b = N_NODES;
        while (a < b) { int m = (a + b) >> 1; if (batch[m] < g) a = m + 1; else b = m; }
        s_lo = a;
        b = N_NODES;
        while (a < b) { int m = (a + b) >> 1; if (batch[m] < g + 1) a = m + 1; else b = m; }
        s_hi = a;
    }
    __syncthreads();
    int lo = s_lo, hi = s_hi;
    int lane = threadIdx.x & 31, wid = threadIdx.x >> 5;
    float acc = 0.f;
    for (int n = lo + wid; n < hi; n += 8)
        acc += g_z[(size_t)n * LAT + lane];
    __shared__ float sh[8][LAT];
    sh[wid][lane] = acc;
    __syncthreads();
    if (wid == 0) {
        float s = 0.f;
        #pragma unroll
        for (int k = 0; k < 8; k++) s += sh[k][lane];
        float cnt = (float)(hi - lo);
        out[g * LAT + lane] = s / fmaxf(cnt, 1.0f);
    }
}

// ---------------- launch: kernel launches ONLY ----------------
extern "C" void kernel_launch(void* const* d_in, const int* in_sizes, int n_in,
                              void* d_out, int out_size)
{
    const float* x     = (const float*)d_in[0];
    const int*   ei    = (const int*)d_in[1];      // int32
    const int*   batch = (const int*)d_in[2];      // int32
    const float* conv1_w = (const float*)d_in[3];
    const float* conv1_b = (const float*)d_in[4];
    const float* conv2_w = (const float*)d_in[5];
    const float* conv2_b = (const float*)d_in[6];
    const float* bn1_g = (const float*)d_in[7];
    const float* bn1_b = (const float*)d_in[8];
    const float* bn1_m = (const float*)d_in[9];
    const float* bn1_v = (const float*)d_in[10];
    const float* bn2_g = (const float*)d_in[11];
    const float* bn2_b = (const float*)d_in[12];
    const float* bn2_m = (const float*)d_in[13];
    const float* bn2_v = (const float*)d_in[14];
    const float* fc1_w = (const float*)d_in[15];
    const float* fc1_b = (const float*)d_in[16];
    const float* bnd_g = (const float*)d_in[17];
    const float* bnd_b = (const float*)d_in[18];
    const float* bnd_m = (const float*)d_in[19];
    const float* bnd_v = (const float*)d_in[20];
    const float* fc2_w = (const float*)d_in[21];
    const float* fc2_b = (const float*)d_in[22];
    float* out = (float*)d_out;

    zero_prep_kernel<<<(N_NODES + 255) / 256, 256>>>(
        conv1_b, bn1_g, bn1_b, bn1_m, bn1_v,
        conv2_b, bn2_g, bn2_b, bn2_m, bn2_v,
        fc1_b,   bnd_g, bnd_b, bnd_m, bnd_v);

    count_kernel<<<(N_EDGES + 255) / 256, 256>>>(ei);
    scanA_kernel<<<NBLK, 256>>>();          // also computes g_dis
    scanB_kernel<<<1, 32>>>();
    scanC_kernel<<<NBLK, 256>>>();
    fill_kernel<<<(N_EDGES + 255) / 256, 256>>>(ei);

    // xs = x * dis[row]  -> g_big
    scale_x_kernel<<<(N_NODES * (IN_CH / 4) + 255) / 256, 256>>>(x);
    // a = dis[n] * sum xs[src]
    agg64_kernel<<<(N_NODES * 32 + 255) / 256, 256>>>();
    // b1 = relu(bn1(a @ W1 + conv1_b))  -> g_big   [TM=8, RPB=64; smem 48KB]
    gemm_kernel<64, 128, 8, 1, 1, 1><<<(N_NODES + 63) / 64, 256>>>(conv1_w, fc2_b, out);
    // h2 = (b1 @ W2) * dis[row]  -> g_h2           [TM=2, RPB=64; smem 48KB]
    gemm_kernel<128, 32, 2, 4, 2, 2><<<(N_NODES + 63) / 64, 256>>>(conv2_w, fc2_b, out);
    // z = relu(bn2(dis[n] * sum h2[src] + conv2_b))
    agg32_kernel<<<(N_NODES * 32 + 255) / 256, 256>>>();
    // d = relu(bnd(z @ fc1_w + fc1_b))  -> g_big   [TM=8, RPB=64; smem 24KB]
    gemm_kernel<32, 128, 8, 2, 3, 1><<<(N_NODES + 63) / 64, 256>>>(fc1_w, fc2_b, out);
    // x_hat = d @ fc2_w + fc2_b -> d_out           [TM=2, RPB=32; smem 48KB]
    gemm_kernel<128, 64, 2, 3, 2, 0><<<(N_NODES + 31) / 32, 256>>>(fc2_w, fc2_b, out);
    // z_graph -> d_out[6.4M:]
    pool_kernel<<<N_GRAPHS, 256>>>(batch, out + (size_t)N_NODES * IN_CH);
}

// round 11
// speedup vs baseline: 1.3581x; 1.0770x over previous
#include <cuda_runtime.h>
#include <cstdint>

// ---------------- problem constants ----------------
constexpr int N_NODES  = 100000;
constexpr int N_EDGES  = 3200000;
constexpr int N_GRAPHS = 64;
constexpr int IN_CH  = 64;
constexpr int HID_CH = 128;
constexpr int LAT    = 32;
constexpr float EPS  = 1e-5f;
constexpr int SCAN_CHUNK = 1024;
constexpr int NBLK = (N_NODES + SCAN_CHUNK - 1) / SCAN_CHUNK;   // 98

// ---------------- scratch (device globals) ----------------
__device__ __align__(16) int   g_count[N_NODES];
__device__ __align__(16) int   g_rowptr[N_NODES + 1];
__device__ __align__(16) int   g_cur[N_NODES];
__device__ __align__(16) int   g_src[N_EDGES];
__device__ __align__(16) int   g_bsum[NBLK];
__device__ __align__(16) int   g_boff[NBLK];
__device__ __align__(16) float g_dis[N_NODES];
__device__ __align__(16) float g_a  [(size_t)N_NODES * IN_CH];   // agg(x*dis)
__device__ __align__(16) float g_xs [(size_t)N_NODES * IN_CH];   // x * dis[row]
__device__ __align__(16) float g_h2 [(size_t)N_NODES * LAT];     // enc out (pre-agg)
__device__ __align__(16) float g_z  [(size_t)N_NODES * LAT];     // z_nodes
__device__ __align__(16) float g_s1[HID_CH];
__device__ __align__(16) float g_t1[HID_CH];
__device__ __align__(16) float g_s2[LAT];
__device__ __align__(16) float g_t2[LAT];
__device__ __align__(16) float g_sd[HID_CH];
__device__ __align__(16) float g_td[HID_CH];

// ---------------- zero counters + BN prep (fused) ----------------
__global__ void zero_prep_kernel(
    const float* __restrict__ conv1_b,
    const float* __restrict__ bn1_g, const float* __restrict__ bn1_b,
    const float* __restrict__ bn1_m, const float* __restrict__ bn1_v,
    const float* __restrict__ conv2_b,
    const float* __restrict__ bn2_g, const float* __restrict__ bn2_b,
    const float* __restrict__ bn2_m, const float* __restrict__ bn2_v,
    const float* __restrict__ fc1_b,
    const float* __restrict__ bnd_g, const float* __restrict__ bnd_b,
    const float* __restrict__ bnd_m, const float* __restrict__ bnd_v)
{
    int i = blockIdx.x * blockDim.x + threadIdx.x;
    if (i < N_NODES) g_count[i] = 0;
    if (blockIdx.x == 0) {
        int c = threadIdx.x;
        if (c < HID_CH) {
            float s = bn1_g[c] * rsqrtf(bn1_v[c] + EPS);
            g_s1[c] = s;
            g_t1[c] = (conv1_b[c] - bn1_m[c]) * s + bn1_b[c];
            float sd = bnd_g[c] * rsqrtf(bnd_v[c] + EPS);
            g_sd[c] = sd;
            g_td[c] = (fc1_b[c] - bnd_m[c]) * sd + bnd_b[c];
        }
        if (c < LAT) {
            float s = bn2_g[c] * rsqrtf(bn2_v[c] + EPS);
            g_s2[c] = s;
            g_t2[c] = (conv2_b[c] - bn2_m[c]) * s + bn2_b[c];
        }
    }
}

// ---------------- CSR build (edge_index is INT32; vectorized int4) ------------
__global__ void count_kernel(const int* __restrict__ ei) {
    int e4 = blockIdx.x * blockDim.x + threadIdx.x;
    if (e4 >= N_EDGES / 4) return;
    int4 c = ((const int4*)(ei + N_EDGES))[e4];
    atomicAdd(&g_count[c.x], 1);
    atomicAdd(&g_count[c.y], 1);
    atomicAdd(&g_count[c.z], 1);
    atomicAdd(&g_count[c.w], 1);
}

// per-chunk sums + dis (fused)
__global__ void scanA_kernel() {
    __shared__ int sh[256];
    int t = threadIdx.x;
    int base = blockIdx.x * SCAN_CHUNK + t * 4;
    int s = 0;
    #pragma unroll
    for (int k = 0; k < 4; k++) {
        int i = base + k;
        if (i < N_NODES) {
            int d = g_count[i];
            s += d;
            g_dis[i] = d > 0 ? rsqrtf((float)d) : 0.0f;
        }
    }
    sh[t] = s; __syncthreads();
    for (int d = 128; d > 0; d >>= 1) {
        if (t < d) sh[t] += sh[t + d];
        __syncthreads();
    }
    if (t == 0) g_bsum[blockIdx.x] = sh[0];
}

// parallel scan of the 98 chunk sums (128 threads, Hillis-Steele)
__global__ void scanB_kernel() {
    __shared__ int sh[128];
    int t = threadIdx.x;
    int v = (t < NBLK) ? g_bsum[t] : 0;
    sh[t] = v; __syncthreads();
    for (int d = 1; d < 128; d <<= 1) {
        int tmp = (t >= d) ? sh[t - d] : 0;
        __syncthreads();
        sh[t] += tmp;
        __syncthreads();
    }
    if (t < NBLK) g_boff[t] = sh[t] - v;           // exclusive
    if (t == NBLK - 1) g_rowptr[N_NODES] = sh[t];
}

__global__ void scanC_kernel() {
    __shared__ int sh[256];
    int t = threadIdx.x;
    int base = blockIdx.x * SCAN_CHUNK + t * 4;
    int v[4]; int s = 0;
    #pragma unroll
    for (int k = 0; k < 4; k++) {
        int i = base + k;
        v[k] = (i < N_NODES) ? g_count[i] : 0;
        s += v[k];
    }
    sh[t] = s; __syncthreads();
    for (int d = 1; d < 256; d <<= 1) {
        int tmp = (t >= d) ? sh[t - d] : 0;
        __syncthreads();
        sh[t] += tmp;
        __syncthreads();
    }
    int off = g_boff[blockIdx.x] + sh[t] - s;   // exclusive
    #pragma unroll
    for (int k = 0; k < 4; k++) {
        int i = base + k;
        if (i < N_NODES) { g_rowptr[i] = off; g_cur[i] = off; off += v[k]; }
    }
}

__global__ void fill_kernel(const int* __restrict__ ei) {
    int e4 = blockIdx.x * blockDim.x + threadIdx.x;
    if (e4 >= N_EDGES / 4) return;
    int4 r = ((const int4*)ei)[e4];
    int4 c = ((const int4*)(ei + N_EDGES))[e4];
    g_src[atomicAdd(&g_cur[c.x], 1)] = r.x;
    g_src[atomicAdd(&g_cur[c.y], 1)] = r.y;
    g_src[atomicAdd(&g_cur[c.z], 1)] = r.z;
    g_src[atomicAdd(&g_cur[c.w], 1)] = r.w;
}

// ---------------- xs = x * dis[row] ------------
__global__ void scale_x_kernel(const float* __restrict__ x) {
    int i = blockIdx.x * 256 + threadIdx.x;                // float4 index
    if (i >= N_NODES * (IN_CH / 4)) return;
    int row = i >> 4;
    float d = g_dis[row];
    float4 v = ((const float4*)x)[i];
    v.x *= d; v.y *= d; v.z *= d; v.w *= d;
    ((float4*)g_xs)[i] = v;
}

// ---------------- agg64: a[n] = dis[n] * sum xs[src]  (warp/node) -------------
__global__ void agg64_kernel() {
    int w = (blockIdx.x * blockDim.x + threadIdx.x) >> 5;
    if (w >= N_NODES) return;
    int lane = threadIdx.x & 31;
    int beg = g_rowptr[w], end = g_rowptr[w + 1];
    float2 acc = make_float2(0.f, 0.f);
    int i = beg;
    for (; i + 32 <= end; i += 32) {
        int myr = g_src[i + lane];
        #pragma unroll
        for (int j = 0; j < 32; j++) {
            int r = __shfl_sync(0xffffffffu, myr, j);
            float2 v = ((const float2*)g_xs)[r * (IN_CH / 2) + lane];
            acc.x += v.x;
            acc.y += v.y;
        }
    }
    if (i < end) {
        int cnt = end - i;
        int myr = (i + lane < end) ? g_src[i + lane] : 0;
        #pragma unroll 4
        for (int j = 0; j < cnt; j++) {
            int r = __shfl_sync(0xffffffffu, myr, j);
            float2 v = ((const float2*)g_xs)[r * (IN_CH / 2) + lane];
            acc.x += v.x;
            acc.y += v.y;
        }
    }
    float dc = g_dis[w];
    acc.x *= dc; acc.y *= dc;
    ((float2*)g_a)[w * (IN_CH / 2) + lane] = acc;
}

// ---------------- agg32: z[n] = relu(bn2(dis[n] * sum h2[src])) ---------------
__global__ void agg32_kernel() {
    int w = (blockIdx.x * blockDim.x + threadIdx.x) >> 5;
    if (w >= N_NODES) return;
    int lane = threadIdx.x & 31;
    int beg = g_rowptr[w], end = g_rowptr[w + 1];
    float acc = 0.f;
    int i = beg;
    for (; i + 32 <= end; i += 32) {
        int myr = g_src[i + lane];
        #pragma unroll
        for (int j = 0; j < 32; j++) {
            int r = __shfl_sync(0xffffffffu, myr, j);
            acc += g_h2[r * LAT + lane];
        }
    }
    if (i < end) {
        int cnt = end - i;
        int myr = (i + lane < end) ? g_src[i + lane] : 0;
        #pragma unroll 4
        for (int j = 0; j < cnt; j++) {
            int r = __shfl_sync(0xffffffffu, myr, j);
            acc += g_h2[r * LAT + lane];
        }
    }
    acc *= g_dis[w];
    g_z[w * LAT + lane] = fmaxf(fmaf(acc, g_s2[lane], g_t2[lane]), 0.f);
}

// ---------------- fused encoder GEMM: h2 = relu(bn1(a@W1)) @ W2 * dis ---------
// stage1 result kept in padded smem (132-float rows); W1 streamed via L1.
constexpr int ERPB = 32;
__global__ void __launch_bounds__(256) enc_gemm_kernel(const float* __restrict__ W1,
                                                       const float* __restrict__ W2)
{
    __shared__ alignas(16) float W2sh[HID_CH * LAT];     // 16 KB
    __shared__ alignas(16) float Xsh[ERPB * IN_CH];      // 8 KB
    __shared__ alignas(16) float B1sh[ERPB * 132];       // 16.5 KB (padded rows)
    const int tid = threadIdx.x;
    const int base = blockIdx.x * ERPB;

    for (int i = tid; i < HID_CH * LAT / 4; i += 256)
        ((float4*)W2sh)[i] = ((const float4*)W2)[i];
    for (int i = tid; i < ERPB * IN_CH / 4; i += 256) {
        int row = (i * 4) >> 6;
        float4 v = make_float4(0.f, 0.f, 0.f, 0.f);
        if (base + row < N_NODES) v = ((const float4*)g_a)[(size_t)base * 16 + i];
        ((float4*)Xsh)[i] = v;
    }
    __syncthreads();

    // stage 1: B1 = relu(bn1(X @ W1)); CQ=32, TM=4
    {
        int cx = tid & 31, ry = tid >> 5;
        float4 acc[4];
        #pragma unroll
        for (int m = 0; m < 4; m++) acc[m] = make_float4(0.f, 0.f, 0.f, 0.f);
        #pragma unroll 8
        for (int k = 0; k < IN_CH; k++) {
            float4 wv = ((const float4*)W1)[k * 32 + cx];     // L1-resident (32 KB)
            #pragma unroll
            for (int m = 0; m < 4; m++) {
                float xv = Xsh[(ry * 4 + m) * IN_CH + k];
                acc[m].x = fmaf(xv, wv.x, acc[m].x);
                acc[m].y = fmaf(xv, wv.y, acc[m].y);
                acc[m].z = fmaf(xv, wv.z, acc[m].z);
                acc[m].w = fmaf(xv, wv.w, acc[m].w);
            }
        }
        float4 sv = ((const float4*)g_s1)[cx];
        float4 tv = ((const float4*)g_t1)[cx];
        #pragma unroll
        for (int m = 0; m < 4; m++) {
            float4 o;
            o.x = fmaxf(fmaf(acc[m].x, sv.x, tv.x), 0.f);
            o.y = fmaxf(fmaf(acc[m].y, sv.y, tv.y), 0.f);
            o.z = fmaxf(fmaf(acc[m].z, sv.z, tv.z), 0.f);
            o.w = fmaxf(fmaf(acc[m].w, sv.w, tv.w), 0.f);
            ((float4*)(B1sh + (ry * 4 + m) * 132))[cx] = o;
        }
    }
    __syncthreads();

    // stage 2: h2 = (B1 @ W2) * dis[row]; CQ=8, TM=1
    {
        int cx = tid & 7, ry = tid >> 3;
        float4 acc = make_float4(0.f, 0.f, 0.f, 0.f);
        #pragma unroll 8
        for (int k = 0; k < HID_CH; k++) {
            float4 wv = ((const float4*)W2sh)[k * 8 + cx];
            float xv = B1sh[ry * 132 + k];
            acc.x = fmaf(xv, wv.x, acc.x);
            acc.y = fmaf(xv, wv.y, acc.y);
            acc.z = fmaf(xv, wv.z, acc.z);
            acc.w = fmaf(xv, wv.w, acc.w);
        }
        int row = base + ry;
        if (row < N_NODES) {
            float d = g_dis[row];
            acc.x *= d; acc.y *= d; acc.z *= d; acc.w *= d;
            ((float4*)g_h2)[(size_t)row * 8 + cx] = acc;
        }
    }
}

// ---------------- fused decoder GEMM: out = relu(bnd(z@W3)) @ W4 + b ----------
constexpr int DRPB = 32;
__global__ void __launch_bounds__(256) dec_gemm_kernel(const float* __restrict__ W3,
                                                       const float* __restrict__ W4,
                                                       const float* __restrict__ b4,
                                                       float* __restrict__ out)
{
    __shared__ alignas(16) float W3sh[LAT * HID_CH];     // 16 KB
    __shared__ alignas(16) float Zsh[DRPB * LAT];        // 4 KB
    __shared__ alignas(16) float Dsh[DRPB * 132];        // 16.5 KB
    const int tid = threadIdx.x;
    const int base = blockIdx.x * DRPB;

    for (int i = tid; i < LAT * HID_CH / 4; i += 256)
        ((float4*)W3sh)[i] = ((const float4*)W3)[i];
    for (int i = tid; i < DRPB * LAT / 4; i += 256) {
        int row = (i * 4) >> 5;
        float4 v = make_float4(0.f, 0.f, 0.f, 0.f);
        if (base + row < N_NODES) v = ((const float4*)g_z)[(size_t)base * 8 + i];
        ((float4*)Zsh)[i] = v;
    }
    __syncthreads();

    // stage 1: D = relu(bnd(Z @ W3)); CQ=32, TM=4
    {
        int cx = tid & 31, ry = tid >> 5;
        float4 acc[4];
        #pragma unroll
        for (int m = 0; m < 4; m++) acc[m] = make_float4(0.f, 0.f, 0.f, 0.f);
        #pragma unroll
        for (int k = 0; k < LAT; k++) {
            float4 wv = ((const float4*)W3sh)[k * 32 + cx];
            #pragma unroll
            for (int m = 0; m < 4; m++) {
                float xv = Zsh[(ry * 4 + m) * LAT + k];
                acc[m].x = fmaf(xv, wv.x, acc[m].x);
                acc[m].y = fmaf(xv, wv.y, acc[m].y);
                acc[m].z = fmaf(xv, wv.z, acc[m].z);
                acc[m].w = fmaf(xv, wv.w, acc[m].w);
            }
        }
        float4 sv = ((const float4*)g_sd)[cx];
        float4 tv = ((const float4*)g_td)[cx];
        #pragma unroll
        for (int m = 0; m < 4; m++) {
            float4 o;
            o.x = fmaxf(fmaf(acc[m].x, sv.x, tv.x), 0.f);
            o.y = fmaxf(fmaf(acc[m].y, sv.y, tv.y), 0.f);
            o.z = fmaxf(fmaf(acc[m].z, sv.z, tv.z), 0.f);
            o.w = fmaxf(fmaf(acc[m].w, sv.w, tv.w), 0.f);
            ((float4*)(Dsh + (ry * 4 + m) * 132))[cx] = o;
        }
    }
    __syncthreads();

    // stage 2: out = D @ W4 + b4; COUT=64, CQ=16, TM=2; W4 via L1 (32 KB)
    {
        int cx = tid & 15, ry = tid >> 4;
        float4 acc[2];
        acc[0] = make_float4(0.f, 0.f, 0.f, 0.f);
        acc[1] = make_float4(0.f, 0.f, 0.f, 0.f);
        #pragma unroll 8
        for (int k = 0; k < HID_CH; k++) {
            float4 wv = ((const float4*)W4)[k * 16 + cx];
            #pragma unroll
            for (int m = 0; m < 2; m++) {
                float xv = Dsh[(ry * 2 + m) * 132 + k];
                acc[m].x = fmaf(xv, wv.x, acc[m].x);
                acc[m].y = fmaf(xv, wv.y, acc[m].y);
                acc[m].z = fmaf(xv, wv.z, acc[m].z);
                acc[m].w = fmaf(xv, wv.w, acc[m].w);
            }
        }
        float4 bv = ((const float4*)b4)[cx];
        #pragma unroll
        for (int m = 0; m < 2; m++) {
            int row = base + ry * 2 + m;
            if (row < N_NODES) {
                float4 o = acc[m];
                o.x += bv.x; o.y += bv.y; o.z += bv.z; o.w += bv.w;
                ((float4*)out)[(size_t)row * 16 + cx] = o;
            }
        }
    }
}

// ---------------- graph mean pool: batch is SORTED int32 ----------------------
__global__ void pool_kernel(const int* __restrict__ batch, float* __restrict__ out) {
    int g = blockIdx.x;
    __shared__ int s_lo, s_hi;
    if (threadIdx.x == 0) {
        int a = 0, b = N_NODES;
        while (a < b) { int m = (a + b) >> 1; if (batch[m] < g) a = m + 1; else b = m; }
        s_lo = a;
        b = N_NODES;
        while (a < b) { int m = (a + b) >> 1; if (batch[m] < g + 1) a = m + 1; else b = m; }
        s_hi = a;
    }
    __syncthreads();
    int lo = s_lo, hi = s_hi;
    int lane = threadIdx.x & 31, wid = threadIdx.x >> 5;
    float acc = 0.f;
    for (int n = lo + wid; n < hi; n += 8)
        acc += g_z[(size_t)n * LAT + lane];
    __shared__ float sh[8][LAT];
    sh[wid][lane] = acc;
    __syncthreads();
    if (wid == 0) {
        float s = 0.f;
        #pragma unroll
        for (int k = 0; k < 8; k++) s += sh[k][lane];
        float cnt = (float)(hi - lo);
        out[g * LAT + lane] = s / fmaxf(cnt, 1.0f);
    }
}

// ---------------- launch: kernel launches ONLY ----------------
extern "C" void kernel_launch(void* const* d_in, const int* in_sizes, int n_in,
                              void* d_out, int out_size)
{
    const float* x     = (const float*)d_in[0];
    const int*   ei    = (const int*)d_in[1];      // int32
    const int*   batch = (const int*)d_in[2];      // int32
    const float* conv1_w = (const float*)d_in[3];
    const float* conv1_b = (const float*)d_in[4];
    const float* conv2_w = (const float*)d_in[5];
    const float* conv2_b = (const float*)d_in[6];
    const float* bn1_g = (const float*)d_in[7];
    const float* bn1_b = (const float*)d_in[8];
    const float* bn1_m = (const float*)d_in[9];
    const float* bn1_v = (const float*)d_in[10];
    const float* bn2_g = (const float*)d_in[11];
    const float* bn2_b = (const float*)d_in[12];
    const float* bn2_m = (const float*)d_in[13];
    const float* bn2_v = (const float*)d_in[14];
    const float* fc1_w = (const float*)d_in[15];
    const float* fc1_b = (const float*)d_in[16];
    const float* bnd_g = (const float*)d_in[17];
    const float* bnd_b = (const float*)d_in[18];
    const float* bnd_m = (const float*)d_in[19];
    const float* bnd_v = (const float*)d_in[20];
    const float* fc2_w = (const float*)d_in[21];
    const float* fc2_b = (const float*)d_in[22];
    float* out = (float*)d_out;

    zero_prep_kernel<<<(N_NODES + 255) / 256, 256>>>(
        conv1_b, bn1_g, bn1_b, bn1_m, bn1_v,
        conv2_b, bn2_g, bn2_b, bn2_m, bn2_v,
        fc1_b,   bnd_g, bnd_b, bnd_m, bnd_v);

    count_kernel<<<(N_EDGES / 4 + 255) / 256, 256>>>(ei);
    scanA_kernel<<<NBLK, 256>>>();          // also computes g_dis
    scanB_kernel<<<1, 128>>>();
    scanC_kernel<<<NBLK, 256>>>();
    fill_kernel<<<(N_EDGES / 4 + 255) / 256, 256>>>(ei);

    // xs = x * dis[row]
    scale_x_kernel<<<(N_NODES * (IN_CH / 4) + 255) / 256, 256>>>(x);
    // a = dis[n] * sum xs[src]
    agg64_kernel<<<(N_NODES * 32 + 255) / 256, 256>>>();
    // h2 = relu(bn1(a@W1 + cb1)) @ W2 * dis[row]   (fused encoder)
    enc_gemm_kernel<<<(N_NODES + ERPB - 1) / ERPB, 256>>>(conv1_w, conv2_w);
    // z = relu(bn2(dis[n] * sum h2[src] + cb2))
    agg32_kernel<<<(N_NODES * 32 + 255) / 256, 256>>>();
    // x_hat = relu(bnd(z@fc1 + b3)) @ fc2 + b4  -> d_out   (fused decoder)
    dec_gemm_kernel<<<(N_NODES + DRPB - 1) / DRPB, 256>>>(fc1_w, fc2_w, fc2_b, out);
    // z_graph -> d_out[6.4M:]
    pool_kernel<<<N_GRAPHS, 256>>>(batch, out + (size_t)N_NODES * IN_CH);
}